// round 13
// baseline (speedup 1.0000x reference)
#include <cuda_runtime.h>
#include <cstdint>
#include <math.h>

#define B_ 16
#define L_ 2048
#define D_ 512
#define H_ 512

typedef unsigned long long ull;

// ---------------- static device scratch (no cudaMalloc allowed) -------------
__device__ float g_pre[(size_t)B_ * L_ * 1024];   // [b][t][fwd 0:512 | bwd 512:1024]
__device__ float g_hs [(size_t)B_ * L_ * 1024];   // same layout
__device__ float g_wcomb[1024 * 512];             // rows 0:512 = Wo_f@Wd_top, 512:1024 = Wo_b@Wd_bot
__device__ float g_bias2[512];

// ---------------- f32x2 helpers ---------------------------------------------
__device__ __forceinline__ ull pk2(float x, float y) {
    ull r; asm("mov.b64 %0,{%1,%2};" : "=l"(r) : "f"(x), "f"(y)); return r;
}
__device__ __forceinline__ float2 up2(ull v) {
    float2 r; asm("mov.b64 {%0,%1},%2;" : "=f"(r.x), "=f"(r.y) : "l"(v)); return r;
}
__device__ __forceinline__ void fm2(ull& d, ull a, ull b) {
    asm("fma.rn.f32x2 %0,%1,%2,%0;" : "+l"(d) : "l"(a), "l"(b));
}
// fast tanh: 1 - 2/(e^{2x}+1); abs err ~1e-6; saturates to +-1 correctly
__device__ __forceinline__ float ftanh(float x) {
    float t = __expf(2.0f * x);
    return 1.0f - __fdividef(2.0f, t + 1.0f);
}

// ---------------- dummy: shifts launch index so ncu -s 5 captures the scan --
__global__ void dummy_kernel() {}

// ---------------- bias2: fold bo_f, bo_b, bd through Wd ---------------------
__global__ void bias2_kernel(const float* __restrict__ Wd, const float* __restrict__ bd,
                             const float* __restrict__ bo_f, const float* __restrict__ bo_b) {
    int o = threadIdx.x;   // 512 threads
    float s = bd[o];
    for (int dd = 0; dd < 512; dd++) {
        s += bo_f[dd] * Wd[dd * 512 + o];
        s += bo_b[dd] * Wd[(512 + dd) * 512 + o];
    }
    g_bias2[o] = s;
}

// ---------------- SGEMM (smem double-buffered): C = A@B + bias --------------
#define TBM 128
#define TBN 128
#define TBK 16
__global__ void __launch_bounds__(256, 2)
sgemm(const float* __restrict__ A, const float* __restrict__ B,
      const float* __restrict__ bias, float* __restrict__ C,
      int M, int N, int K) {
    __shared__ float As[2][TBK][TBM + 4];
    __shared__ float Bs[2][TBK][TBN + 4];

    int tid = threadIdx.x;
    int bx = blockIdx.x, by = blockIdx.y;
    int tx = tid & 15, ty = tid >> 4;

    int mA  = tid >> 2;
    int kcA = tid & 3;
    int kbB = tid >> 5;
    int ncB = tid & 31;

    ull acc[8][4];
    #pragma unroll
    for (int i = 0; i < 8; i++)
        #pragma unroll
        for (int j = 0; j < 4; j++) acc[i][j] = 0ull;

    const float* Ag = A + (size_t)(by * TBM + mA) * K + kcA * 4;
    const float* Bg = B + (size_t)kbB * N + bx * TBN + ncB * 4;

    {
        float4 a0 = *(const float4*)(Ag);
        float4 a1 = *(const float4*)(Ag + (size_t)64 * K);
        float4 b0 = *(const float4*)(Bg);
        float4 b1 = *(const float4*)(Bg + (size_t)8 * N);
        As[0][kcA * 4 + 0][mA] = a0.x;  As[0][kcA * 4 + 1][mA] = a0.y;
        As[0][kcA * 4 + 2][mA] = a0.z;  As[0][kcA * 4 + 3][mA] = a0.w;
        As[0][kcA * 4 + 0][mA + 64] = a1.x;  As[0][kcA * 4 + 1][mA + 64] = a1.y;
        As[0][kcA * 4 + 2][mA + 64] = a1.z;  As[0][kcA * 4 + 3][mA + 64] = a1.w;
        *(float4*)&Bs[0][kbB][ncB * 4]     = b0;
        *(float4*)&Bs[0][kbB + 8][ncB * 4] = b1;
    }
    __syncthreads();

    int iters = K / TBK;
    for (int it = 0; it < iters; it++) {
        int buf = it & 1;
        bool more = (it + 1 < iters);
        float4 na0, na1, nb0, nb1;
        if (more) {
            int k0 = (it + 1) * TBK;
            na0 = *(const float4*)(Ag + k0);
            na1 = *(const float4*)(Ag + (size_t)64 * K + k0);
            nb0 = *(const float4*)(Bg + (size_t)k0 * N);
            nb1 = *(const float4*)(Bg + (size_t)(k0 + 8) * N);
        }

        #pragma unroll
        for (int kk = 0; kk < TBK; kk++) {
            float4 al = *(float4*)&As[buf][kk][ty * 8];
            float4 ah = *(float4*)&As[buf][kk][ty * 8 + 4];
            float4 bl = *(float4*)&Bs[buf][kk][tx * 8];
            float4 bh = *(float4*)&Bs[buf][kk][tx * 8 + 4];
            ull bb[4] = { pk2(bl.x, bl.y), pk2(bl.z, bl.w),
                          pk2(bh.x, bh.y), pk2(bh.z, bh.w) };
            float av[8] = { al.x, al.y, al.z, al.w, ah.x, ah.y, ah.z, ah.w };
            #pragma unroll
            for (int i = 0; i < 8; i++) {
                ull ad = pk2(av[i], av[i]);
                #pragma unroll
                for (int jn = 0; jn < 4; jn++) fm2(acc[i][jn], ad, bb[jn]);
            }
        }

        if (more) {
            int nb = buf ^ 1;
            As[nb][kcA * 4 + 0][mA] = na0.x;  As[nb][kcA * 4 + 1][mA] = na0.y;
            As[nb][kcA * 4 + 2][mA] = na0.z;  As[nb][kcA * 4 + 3][mA] = na0.w;
            As[nb][kcA * 4 + 0][mA + 64] = na1.x;  As[nb][kcA * 4 + 1][mA + 64] = na1.y;
            As[nb][kcA * 4 + 2][mA + 64] = na1.z;  As[nb][kcA * 4 + 3][mA + 64] = na1.w;
            *(float4*)&Bs[nb][kbB][ncB * 4]     = nb0;
            *(float4*)&Bs[nb][kbB + 8][ncB * 4] = nb1;
            __syncthreads();
        }
    }

    int mBase = by * TBM + ty * 8;
    int nBase = bx * TBN + tx * 8;
    float4 bvl = make_float4(0.f, 0.f, 0.f, 0.f), bvh = bvl;
    if (bias) {
        bvl = *(const float4*)(bias + nBase);
        bvh = *(const float4*)(bias + nBase + 4);
    }
    #pragma unroll
    for (int i = 0; i < 8; i++) {
        float2 p0 = up2(acc[i][0]), p1 = up2(acc[i][1]);
        float2 p2 = up2(acc[i][2]), p3 = up2(acc[i][3]);
        float4 c0 = make_float4(p0.x + bvl.x, p0.y + bvl.y, p1.x + bvl.z, p1.y + bvl.w);
        float4 c1 = make_float4(p2.x + bvh.x, p2.y + bvh.y, p3.x + bvh.z, p3.y + bvh.w);
        float* cp = C + (size_t)(mBase + i) * N + nBase;
        *(float4*)cp = c0;
        *(float4*)(cp + 4) = c1;
    }
}

// ---- pre-GEMM: pre = x @ [Wx_f | Wx_b] + [b_f|b_b], pack fused via bx ------
__global__ void __launch_bounds__(256, 2)
sgemm_pre(const float* __restrict__ A,
          const float* __restrict__ Wxf, const float* __restrict__ Wxb,
          const float* __restrict__ bf,  const float* __restrict__ bb,
          float* __restrict__ C) {
    const int K = 512, NB = 512, NC = 1024;
    __shared__ float As[2][TBK][TBM + 4];
    __shared__ float Bs[2][TBK][TBN + 4];

    int tid = threadIdx.x;
    int bx = blockIdx.x, by = blockIdx.y;
    int tx = tid & 15, ty = tid >> 4;

    const float* B    = (bx < 4) ? Wxf : Wxb;
    const float* bias = (bx < 4) ? bf  : bb;
    int nb0 = (bx & 3) * TBN;

    int mA  = tid >> 2;
    int kcA = tid & 3;
    int kbB = tid >> 5;
    int ncB = tid & 31;

    ull acc[8][4];
    #pragma unroll
    for (int i = 0; i < 8; i++)
        #pragma unroll
        for (int j = 0; j < 4; j++) acc[i][j] = 0ull;

    const float* Ag = A + (size_t)(by * TBM + mA) * K + kcA * 4;
    const float* Bg = B + (size_t)kbB * NB + nb0 + ncB * 4;

    {
        float4 a0 = *(const float4*)(Ag);
        float4 a1 = *(const float4*)(Ag + (size_t)64 * K);
        float4 b0 = *(const float4*)(Bg);
        float4 b1 = *(const float4*)(Bg + (size_t)8 * NB);
        As[0][kcA * 4 + 0][mA] = a0.x;  As[0][kcA * 4 + 1][mA] = a0.y;
        As[0][kcA * 4 + 2][mA] = a0.z;  As[0][kcA * 4 + 3][mA] = a0.w;
        As[0][kcA * 4 + 0][mA + 64] = a1.x;  As[0][kcA * 4 + 1][mA + 64] = a1.y;
        As[0][kcA * 4 + 2][mA + 64] = a1.z;  As[0][kcA * 4 + 3][mA + 64] = a1.w;
        *(float4*)&Bs[0][kbB][ncB * 4]     = b0;
        *(float4*)&Bs[0][kbB + 8][ncB * 4] = b1;
    }
    __syncthreads();

    int iters = K / TBK;
    for (int it = 0; it < iters; it++) {
        int buf = it & 1;
        bool more = (it + 1 < iters);
        float4 na0, na1, nb0v, nb1v;
        if (more) {
            int k0 = (it + 1) * TBK;
            na0 = *(const float4*)(Ag + k0);
            na1 = *(const float4*)(Ag + (size_t)64 * K + k0);
            nb0v = *(const float4*)(Bg + (size_t)k0 * NB);
            nb1v = *(const float4*)(Bg + (size_t)(k0 + 8) * NB);
        }

        #pragma unroll
        for (int kk = 0; kk < TBK; kk++) {
            float4 al = *(float4*)&As[buf][kk][ty * 8];
            float4 ah = *(float4*)&As[buf][kk][ty * 8 + 4];
            float4 bl = *(float4*)&Bs[buf][kk][tx * 8];
            float4 bh = *(float4*)&Bs[buf][kk][tx * 8 + 4];
            ull bb2[4] = { pk2(bl.x, bl.y), pk2(bl.z, bl.w),
                           pk2(bh.x, bh.y), pk2(bh.z, bh.w) };
            float av[8] = { al.x, al.y, al.z, al.w, ah.x, ah.y, ah.z, ah.w };
            #pragma unroll
            for (int i = 0; i < 8; i++) {
                ull ad = pk2(av[i], av[i]);
                #pragma unroll
                for (int jn = 0; jn < 4; jn++) fm2(acc[i][jn], ad, bb2[jn]);
            }
        }

        if (more) {
            int nbuf = buf ^ 1;
            As[nbuf][kcA * 4 + 0][mA] = na0.x;  As[nbuf][kcA * 4 + 1][mA] = na0.y;
            As[nbuf][kcA * 4 + 2][mA] = na0.z;  As[nbuf][kcA * 4 + 3][mA] = na0.w;
            As[nbuf][kcA * 4 + 0][mA + 64] = na1.x;  As[nbuf][kcA * 4 + 1][mA + 64] = na1.y;
            As[nbuf][kcA * 4 + 2][mA + 64] = na1.z;  As[nbuf][kcA * 4 + 3][mA + 64] = na1.w;
            *(float4*)&Bs[nbuf][kbB][ncB * 4]     = nb0v;
            *(float4*)&Bs[nbuf][kbB + 8][ncB * 4] = nb1v;
            __syncthreads();
        }
    }

    int mBase = by * TBM + ty * 8;
    int nIn   = nb0 + tx * 8;
    int nOut  = bx * TBN + tx * 8;
    float4 bvl = *(const float4*)(bias + nIn);
    float4 bvh = *(const float4*)(bias + nIn + 4);
    #pragma unroll
    for (int i = 0; i < 8; i++) {
        float2 p0 = up2(acc[i][0]), p1 = up2(acc[i][1]);
        float2 p2 = up2(acc[i][2]), p3 = up2(acc[i][3]);
        float4 c0 = make_float4(p0.x + bvl.x, p0.y + bvl.y, p1.x + bvl.z, p1.y + bvl.w);
        float4 c1 = make_float4(p2.x + bvh.x, p2.y + bvh.y, p3.x + bvh.z, p3.y + bvh.w);
        float* cp = C + (size_t)(mBase + i) * NC + nOut;
        *(float4*)cp = c0;
        *(float4*)(cp + 4) = c1;
    }
}

// ---------------- recurrence: shfl-reduce compute + R7 bulk-copy transport --
// 16 clusters x 8 CTAs. hbuf [buf2][kseg8][b2][64]; peer slice = 512B (as R7).
// Lane layout: kseg = l&7 (k in [64*kseg,+64)), jl = wp*4 + (l>>3).
// Bank-conflict-free via rotated chunks: lane reads 16B chunk (c+kseg)&15;
// weights loaded pre-rotated so w[] keeps compile-time indices.
// Reduce: 3x shfl.xor over kseg bits -> all 8 lanes hold full dots.
// kseg==0 lanes: ftanh, stage write, g_hs write. One __syncthreads, then
// threads 0-7 each issue ONE 512B cp.async.bulk to peer tid (R7 transport,
// aggregate double-buffered tx mbar, expect 4096).

__device__ __forceinline__ void mbar_wait_tx(uint32_t mbar, uint32_t parity) {
    uint32_t done;
    asm volatile("{\n\t.reg .pred p;\n\t"
                 "mbarrier.try_wait.parity.acquire.cta.shared::cta.b64 p, [%1], %2;\n\t"
                 "selp.b32 %0, 1, 0, p;\n\t}"
                 : "=r"(done) : "r"(mbar), "r"(parity) : "memory");
    if (!done) {
        asm volatile("{\n\t.reg .pred P1;\n\t"
                     "WL_%=:\n\t"
                     "mbarrier.try_wait.parity.acquire.cta.shared::cta.b64 P1, [%0], %1, 0x989680;\n\t"
                     "@P1 bra.uni WD_%=;\n\t"
                     "bra.uni WL_%=;\n\t"
                     "WD_%=:\n\t}"
                     :: "r"(mbar), "r"(parity) : "memory");
    }
}

__global__ void __launch_bounds__(512, 1) __cluster_dims__(8, 1, 1)
rnn_scan(const float* __restrict__ Wh_f, const float* __restrict__ Wh_b) {
    __shared__ __align__(16) float hbuf[2048];   // [buf2][kseg8][b2][64] = 8KB
    __shared__ __align__(16) float stage[256];   // [par2][b2][64] = 2x512B
    __shared__ __align__(8)  ull  mb[2];

    int tid  = threadIdx.x;
    int bid  = blockIdx.x;
    int rank = bid & 7;
    int cid  = bid >> 3;
    int dir  = cid >> 3;
    int b0   = (cid & 7) * 2;
    int jbase = rank * 64;
    const float* __restrict__ Wh = dir ? Wh_b : Wh_f;

    int l    = tid & 31, wp = tid >> 5;
    int kseg = l & 7;
    int jl   = wp * 4 + (l >> 3);
    int jg   = jbase + jl;
    int kb   = kseg * 64;

    // weights pre-rotated: w[2c],w[2c+1] hold k-pairs of chunk (c+kseg)&15
    ull w[32];
    #pragma unroll
    for (int c = 0; c < 16; c++) {
        int ch = (c + kseg) & 15;
        int k  = kb + ch * 4;
        w[2*c]     = pk2(__ldg(&Wh[(size_t)(k + 0) * H_ + jg]),
                         __ldg(&Wh[(size_t)(k + 1) * H_ + jg]));
        w[2*c + 1] = pk2(__ldg(&Wh[(size_t)(k + 2) * H_ + jg]),
                         __ldg(&Wh[(size_t)(k + 3) * H_ + jg]));
    }

    for (int i = tid; i < 2048; i += 512) hbuf[i] = 0.f;

    uint32_t hb_s = (uint32_t)__cvta_generic_to_shared(hbuf);
    uint32_t st_s = (uint32_t)__cvta_generic_to_shared(stage);
    uint32_t mb_s = (uint32_t)__cvta_generic_to_shared(mb);

    if (tid == 0) {
        asm volatile("mbarrier.init.shared.b64 [%0], 1;" :: "r"(mb_s)     : "memory");
        asm volatile("mbarrier.init.shared.b64 [%0], 1;" :: "r"(mb_s + 8) : "memory");
        asm volatile("mbarrier.arrive.expect_tx.shared.b64 _, [%0], %1;"
                     :: "r"(mb_s + 8), "r"(4096u) : "memory");
        asm volatile("mbarrier.arrive.expect_tx.shared.b64 _, [%0], %1;"
                     :: "r"(mb_s), "r"(4096u) : "memory");
    }
    __syncthreads();
    asm volatile("barrier.cluster.arrive.aligned;" ::: "memory");
    asm volatile("barrier.cluster.wait.aligned;"   ::: "memory");

    // peer hbuf base for MY copy target (thread r copies to peer r)
    uint32_t pbme;
    {
        int tgt = tid & 7;
        asm("mapa.shared::cluster.u32 %0, %1, %2;" : "=r"(pbme) : "r"(hb_s), "r"(tgt));
    }
    uint32_t dmb = mb_s - hb_s;

    bool isres = (kseg == 0);
    const float* pre0 = &g_pre[(size_t)b0       * L_ * 1024 + dir * 512 + jg];
    const float* pre1 = &g_pre[(size_t)(b0 + 1) * L_ * 1024 + dir * 512 + jg];
    float* hs0 = &g_hs[(size_t)b0       * L_ * 1024 + dir * 512 + jg];
    float* hs1 = &g_hs[(size_t)(b0 + 1) * L_ * 1024 + dir * 512 + jg];
    int t0 = dir ? (L_ - 1) : 0;
    float pv0 = 0.f, pv1 = 0.f;
    if (isres) {
        pv0 = __ldg(pre0 + (size_t)t0 * 1024);
        pv1 = __ldg(pre1 + (size_t)t0 * 1024);
    }

    for (int s = 0; s < L_; s++) {
        int t = dir ? (L_ - 1 - s) : s;

        if (s) {
            uint32_t par = (s & 1) ? ((s >> 1) & 1) : (((s >> 1) + 1) & 1);
            mbar_wait_tx(mb_s + 8 * (s & 1), par);
            if (tid == 0 && s + 2 < L_)   // re-arm this buffer for step s+2
                asm volatile("mbarrier.arrive.expect_tx.shared.b64 _, [%0], %1;"
                             :: "r"(mb_s + 8 * (s & 1)), "r"(4096u) : "memory");
        }

        // prefetch next step's pre (hidden under compute)
        float nv0 = 0.f, nv1 = 0.f;
        if (isres && s + 1 < L_) {
            int tn = dir ? (L_ - 2 - s) : (s + 1);
            nv0 = __ldg(pre0 + (size_t)tn * 1024);
            nv1 = __ldg(pre1 + (size_t)tn * 1024);
        }

        // ---- dots over k in [kb, kb+64), both batches; rotated chunks ------
        const float* hp = hbuf + (s & 1) * 1024 + kseg * 128;
        ull a0 = 0ull, a1 = 0ull, a2 = 0ull, a3 = 0ull;
        #pragma unroll
        for (int c = 0; c < 16; c++) {
            int off = ((c + kseg) & 15) * 4;
            ulonglong2 h0 = *(const ulonglong2*)(hp + off);        // batch 0
            ulonglong2 h1 = *(const ulonglong2*)(hp + 64 + off);   // batch 1
            fm2(a0, w[2*c],     h0.x);
            fm2(a1, w[2*c + 1], h0.y);
            fm2(a2, w[2*c],     h1.x);
            fm2(a3, w[2*c + 1], h1.y);
        }
        float2 u0 = up2(a0), u1 = up2(a1), u2 = up2(a2), u3 = up2(a3);
        float r0 = (u0.x + u0.y) + (u1.x + u1.y);
        float r1 = (u2.x + u2.y) + (u3.x + u3.y);
        r0 += __shfl_xor_sync(0xffffffffu, r0, 1);
        r1 += __shfl_xor_sync(0xffffffffu, r1, 1);
        r0 += __shfl_xor_sync(0xffffffffu, r0, 2);
        r1 += __shfl_xor_sync(0xffffffffu, r1, 2);
        r0 += __shfl_xor_sync(0xffffffffu, r0, 4);
        r1 += __shfl_xor_sync(0xffffffffu, r1, 4);

        uint32_t nxt = (uint32_t)((s + 1) & 1);
        if (isres) {
            float hn0 = ftanh(r0 + pv0);
            float hn1 = ftanh(r1 + pv1);
            stage[nxt * 128 + jl]      = hn0;
            stage[nxt * 128 + 64 + jl] = hn1;
            hs0[(size_t)t * 1024] = hn0;
            hs1[(size_t)t * 1024] = hn1;
        }
        pv0 = nv0; pv1 = nv1;

        if (s + 1 < L_) {
            __syncthreads();
            if (tid < 8) {
                asm volatile("fence.proxy.async.shared::cta;" ::: "memory");
                uint32_t src = st_s + nxt * 512;
                uint32_t dst = pbme + nxt * 4096 + (uint32_t)rank * 512;
                uint32_t bar = pbme + dmb + 8 * nxt;
                asm volatile(
                    "cp.async.bulk.shared::cluster.shared::cta.mbarrier::complete_tx::bytes "
                    "[%0], [%1], %2, [%3];"
                    :: "r"(dst), "r"(src), "r"(512u), "r"(bar) : "memory");
            }
        }
    }
    asm volatile("barrier.cluster.arrive.aligned;" ::: "memory");
    asm volatile("barrier.cluster.wait.aligned;"   ::: "memory");
}

// ---------------- host ------------------------------------------------------
extern "C" void kernel_launch(void* const* d_in, const int* in_sizes, int n_in,
                              void* d_out, int out_size) {
    const float* x    = (const float*)d_in[0];
    // d_in[1] = c (unused by reference)
    const float* Wx_f = (const float*)d_in[2];
    const float* Wh_f = (const float*)d_in[3];
    const float* b_f  = (const float*)d_in[4];
    const float* Wo_f = (const float*)d_in[5];
    const float* bo_f = (const float*)d_in[6];
    const float* Wx_b = (const float*)d_in[7];
    const float* Wh_b = (const float*)d_in[8];
    const float* b_b  = (const float*)d_in[9];
    const float* Wo_b = (const float*)d_in[10];
    const float* bo_b = (const float*)d_in[11];
    const float* Wd   = (const float*)d_in[12];
    const float* bd   = (const float*)d_in[13];
    float* out = (float*)d_out;

    void *p_pre, *p_hs, *p_wc, *p_b2;
    cudaGetSymbolAddress(&p_pre, g_pre);
    cudaGetSymbolAddress(&p_hs,  g_hs);
    cudaGetSymbolAddress(&p_wc,  g_wcomb);
    cudaGetSymbolAddress(&p_b2,  g_bias2);

    static cudaStream_t s1 = nullptr;
    static cudaEvent_t evFork = nullptr, evJoin = nullptr;
    if (!s1) {
        cudaStreamCreateWithFlags(&s1, cudaStreamNonBlocking);
        cudaEventCreateWithFlags(&evFork, cudaEventDisableTiming);
        cudaEventCreateWithFlags(&evJoin, cudaEventDisableTiming);
    }

    // kernel launch #1: pre = x @ [Wx_f|Wx_b] + [b_f|b_b]
    {
        dim3 g(8, (B_ * L_) / TBM);
        sgemm_pre<<<g, 256>>>(x, Wx_f, Wx_b, b_f, b_b, (float*)p_pre);
    }
    cudaEventRecord(evFork, 0);

    // kernel launches #2-#5: dummies (so rnn_scan is the 6th launch -> ncu -s 5)
    dummy_kernel<<<1, 32>>>();
    dummy_kernel<<<1, 32>>>();
    dummy_kernel<<<1, 32>>>();
    dummy_kernel<<<1, 32>>>();

    // kernel launch #6: bidirectional scan
    {
        cudaLaunchConfig_t cfg = {};
        cfg.gridDim = dim3(128, 1, 1);
        cfg.blockDim = dim3(512, 1, 1);
        cfg.dynamicSmemBytes = 0;
        cfg.stream = 0;
        cudaLaunchAttribute at[1];
        at[0].id = cudaLaunchAttributeClusterDimension;
        at[0].val.clusterDim.x = 8; at[0].val.clusterDim.y = 1; at[0].val.clusterDim.z = 1;
        cfg.attrs = at;
        cfg.numAttrs = 1;
        cudaLaunchKernelEx(&cfg, rnn_scan, Wh_f, Wh_b);
    }

    // side chain on s1 (independent; overlaps the scan on spare SMs)
    cudaStreamWaitEvent(s1, evFork, 0);
    {
        dim3 g(512 / TBN, 512 / TBM);
        sgemm<<<g, 256, 0, s1>>>(Wo_f, Wd, nullptr, (float*)p_wc, 512, 512, 512);
        sgemm<<<g, 256, 0, s1>>>(Wo_b, Wd + 512 * 512, nullptr,
                                 (float*)p_wc + 512 * 512, 512, 512, 512);
    }
    bias2_kernel<<<1, 512, 0, s1>>>(Wd, bd, bo_f, bo_b);

    // join side chain before the final GEMM
    cudaEventRecord(evJoin, s1);
    cudaStreamWaitEvent(0, evJoin, 0);

    // final GEMM: out = hs @ Wcomb + bias2
    {
        dim3 g(512 / TBN, (B_ * L_) / TBM);
        sgemm<<<g, 256>>>((const float*)p_hs, (const float*)p_wc,
                          (const float*)p_b2, out, B_ * L_, 512, 1024);
    }
}

// round 14
// speedup vs baseline: 1.4136x; 1.4136x over previous
#include <cuda_runtime.h>
#include <cstdint>
#include <math.h>

#define B_ 16
#define L_ 2048
#define D_ 512
#define H_ 512

typedef unsigned long long ull;

// ---------------- static device scratch (no cudaMalloc allowed) -------------
__device__ float g_pre[(size_t)B_ * L_ * 1024];   // [b][t][fwd 0:512 | bwd 512:1024]
__device__ float g_hs [(size_t)B_ * L_ * 1024];   // same layout
__device__ float g_wcomb[1024 * 512];             // rows 0:512 = Wo_f@Wd_top, 512:1024 = Wo_b@Wd_bot
__device__ float g_bias2[512];

// ---------------- f32x2 helpers ---------------------------------------------
__device__ __forceinline__ ull pk2(float x, float y) {
    ull r; asm("mov.b64 %0,{%1,%2};" : "=l"(r) : "f"(x), "f"(y)); return r;
}
__device__ __forceinline__ float2 up2(ull v) {
    float2 r; asm("mov.b64 {%0,%1},%2;" : "=f"(r.x), "=f"(r.y) : "l"(v)); return r;
}
__device__ __forceinline__ void fm2(ull& d, ull a, ull b) {
    asm("fma.rn.f32x2 %0,%1,%2,%0;" : "+l"(d) : "l"(a), "l"(b));
}
// fast tanh: 1 - 2/(e^{2x}+1); abs err ~1e-6; saturates to +-1 correctly
__device__ __forceinline__ float ftanh(float x) {
    float t = __expf(2.0f * x);
    return 1.0f - __fdividef(2.0f, t + 1.0f);
}

// ---------------- bias2: fold bo_f, bo_b, bd through Wd ---------------------
__global__ void bias2_kernel(const float* __restrict__ Wd, const float* __restrict__ bd,
                             const float* __restrict__ bo_f, const float* __restrict__ bo_b) {
    int o = threadIdx.x;   // 512 threads
    float s = bd[o];
    for (int dd = 0; dd < 512; dd++) {
        s += bo_f[dd] * Wd[dd * 512 + o];
        s += bo_b[dd] * Wd[(512 + dd) * 512 + o];
    }
    g_bias2[o] = s;
}

// ---------------- SGEMM (smem double-buffered): C = A@B + bias --------------
#define TBM 128
#define TBN 128
#define TBK 16
__global__ void __launch_bounds__(256, 2)
sgemm(const float* __restrict__ A, const float* __restrict__ B,
      const float* __restrict__ bias, float* __restrict__ C,
      int M, int N, int K) {
    __shared__ float As[2][TBK][TBM + 4];
    __shared__ float Bs[2][TBK][TBN + 4];

    int tid = threadIdx.x;
    int bx = blockIdx.x, by = blockIdx.y;
    int tx = tid & 15, ty = tid >> 4;

    int mA  = tid >> 2;
    int kcA = tid & 3;
    int kbB = tid >> 5;
    int ncB = tid & 31;

    ull acc[8][4];
    #pragma unroll
    for (int i = 0; i < 8; i++)
        #pragma unroll
        for (int j = 0; j < 4; j++) acc[i][j] = 0ull;

    const float* Ag = A + (size_t)(by * TBM + mA) * K + kcA * 4;
    const float* Bg = B + (size_t)kbB * N + bx * TBN + ncB * 4;

    {
        float4 a0 = *(const float4*)(Ag);
        float4 a1 = *(const float4*)(Ag + (size_t)64 * K);
        float4 b0 = *(const float4*)(Bg);
        float4 b1 = *(const float4*)(Bg + (size_t)8 * N);
        As[0][kcA * 4 + 0][mA] = a0.x;  As[0][kcA * 4 + 1][mA] = a0.y;
        As[0][kcA * 4 + 2][mA] = a0.z;  As[0][kcA * 4 + 3][mA] = a0.w;
        As[0][kcA * 4 + 0][mA + 64] = a1.x;  As[0][kcA * 4 + 1][mA + 64] = a1.y;
        As[0][kcA * 4 + 2][mA + 64] = a1.z;  As[0][kcA * 4 + 3][mA + 64] = a1.w;
        *(float4*)&Bs[0][kbB][ncB * 4]     = b0;
        *(float4*)&Bs[0][kbB + 8][ncB * 4] = b1;
    }
    __syncthreads();

    int iters = K / TBK;
    for (int it = 0; it < iters; it++) {
        int buf = it & 1;
        bool more = (it + 1 < iters);
        float4 na0, na1, nb0, nb1;
        if (more) {
            int k0 = (it + 1) * TBK;
            na0 = *(const float4*)(Ag + k0);
            na1 = *(const float4*)(Ag + (size_t)64 * K + k0);
            nb0 = *(const float4*)(Bg + (size_t)k0 * N);
            nb1 = *(const float4*)(Bg + (size_t)(k0 + 8) * N);
        }

        #pragma unroll
        for (int kk = 0; kk < TBK; kk++) {
            float4 al = *(float4*)&As[buf][kk][ty * 8];
            float4 ah = *(float4*)&As[buf][kk][ty * 8 + 4];
            float4 bl = *(float4*)&Bs[buf][kk][tx * 8];
            float4 bh = *(float4*)&Bs[buf][kk][tx * 8 + 4];
            ull bb[4] = { pk2(bl.x, bl.y), pk2(bl.z, bl.w),
                          pk2(bh.x, bh.y), pk2(bh.z, bh.w) };
            float av[8] = { al.x, al.y, al.z, al.w, ah.x, ah.y, ah.z, ah.w };
            #pragma unroll
            for (int i = 0; i < 8; i++) {
                ull ad = pk2(av[i], av[i]);
                #pragma unroll
                for (int jn = 0; jn < 4; jn++) fm2(acc[i][jn], ad, bb[jn]);
            }
        }

        if (more) {
            int nb = buf ^ 1;
            As[nb][kcA * 4 + 0][mA] = na0.x;  As[nb][kcA * 4 + 1][mA] = na0.y;
            As[nb][kcA * 4 + 2][mA] = na0.z;  As[nb][kcA * 4 + 3][mA] = na0.w;
            As[nb][kcA * 4 + 0][mA + 64] = na1.x;  As[nb][kcA * 4 + 1][mA + 64] = na1.y;
            As[nb][kcA * 4 + 2][mA + 64] = na1.z;  As[nb][kcA * 4 + 3][mA + 64] = na1.w;
            *(float4*)&Bs[nb][kbB][ncB * 4]     = nb0;
            *(float4*)&Bs[nb][kbB + 8][ncB * 4] = nb1;
            __syncthreads();
        }
    }

    int mBase = by * TBM + ty * 8;
    int nBase = bx * TBN + tx * 8;
    float4 bvl = make_float4(0.f, 0.f, 0.f, 0.f), bvh = bvl;
    if (bias) {
        bvl = *(const float4*)(bias + nBase);
        bvh = *(const float4*)(bias + nBase + 4);
    }
    #pragma unroll
    for (int i = 0; i < 8; i++) {
        float2 p0 = up2(acc[i][0]), p1 = up2(acc[i][1]);
        float2 p2 = up2(acc[i][2]), p3 = up2(acc[i][3]);
        float4 c0 = make_float4(p0.x + bvl.x, p0.y + bvl.y, p1.x + bvl.z, p1.y + bvl.w);
        float4 c1 = make_float4(p2.x + bvh.x, p2.y + bvh.y, p3.x + bvh.z, p3.y + bvh.w);
        float* cp = C + (size_t)(mBase + i) * N + nBase;
        *(float4*)cp = c0;
        *(float4*)(cp + 4) = c1;
    }
}

// ---- pre-GEMM: pre = x @ [Wx_f | Wx_b] + [b_f|b_b], pack fused via bx ------
__global__ void __launch_bounds__(256, 2)
sgemm_pre(const float* __restrict__ A,
          const float* __restrict__ Wxf, const float* __restrict__ Wxb,
          const float* __restrict__ bf,  const float* __restrict__ bb,
          float* __restrict__ C) {
    const int K = 512, NB = 512, NC = 1024;
    __shared__ float As[2][TBK][TBM + 4];
    __shared__ float Bs[2][TBK][TBN + 4];

    int tid = threadIdx.x;
    int bx = blockIdx.x, by = blockIdx.y;
    int tx = tid & 15, ty = tid >> 4;

    const float* B    = (bx < 4) ? Wxf : Wxb;
    const float* bias = (bx < 4) ? bf  : bb;
    int nb0 = (bx & 3) * TBN;

    int mA  = tid >> 2;
    int kcA = tid & 3;
    int kbB = tid >> 5;
    int ncB = tid & 31;

    ull acc[8][4];
    #pragma unroll
    for (int i = 0; i < 8; i++)
        #pragma unroll
        for (int j = 0; j < 4; j++) acc[i][j] = 0ull;

    const float* Ag = A + (size_t)(by * TBM + mA) * K + kcA * 4;
    const float* Bg = B + (size_t)kbB * NB + nb0 + ncB * 4;

    {
        float4 a0 = *(const float4*)(Ag);
        float4 a1 = *(const float4*)(Ag + (size_t)64 * K);
        float4 b0 = *(const float4*)(Bg);
        float4 b1 = *(const float4*)(Bg + (size_t)8 * NB);
        As[0][kcA * 4 + 0][mA] = a0.x;  As[0][kcA * 4 + 1][mA] = a0.y;
        As[0][kcA * 4 + 2][mA] = a0.z;  As[0][kcA * 4 + 3][mA] = a0.w;
        As[0][kcA * 4 + 0][mA + 64] = a1.x;  As[0][kcA * 4 + 1][mA + 64] = a1.y;
        As[0][kcA * 4 + 2][mA + 64] = a1.z;  As[0][kcA * 4 + 3][mA + 64] = a1.w;
        *(float4*)&Bs[0][kbB][ncB * 4]     = b0;
        *(float4*)&Bs[0][kbB + 8][ncB * 4] = b1;
    }
    __syncthreads();

    int iters = K / TBK;
    for (int it = 0; it < iters; it++) {
        int buf = it & 1;
        bool more = (it + 1 < iters);
        float4 na0, na1, nb0v, nb1v;
        if (more) {
            int k0 = (it + 1) * TBK;
            na0 = *(const float4*)(Ag + k0);
            na1 = *(const float4*)(Ag + (size_t)64 * K + k0);
            nb0v = *(const float4*)(Bg + (size_t)k0 * NB);
            nb1v = *(const float4*)(Bg + (size_t)(k0 + 8) * NB);
        }

        #pragma unroll
        for (int kk = 0; kk < TBK; kk++) {
            float4 al = *(float4*)&As[buf][kk][ty * 8];
            float4 ah = *(float4*)&As[buf][kk][ty * 8 + 4];
            float4 bl = *(float4*)&Bs[buf][kk][tx * 8];
            float4 bh = *(float4*)&Bs[buf][kk][tx * 8 + 4];
            ull bb2[4] = { pk2(bl.x, bl.y), pk2(bl.z, bl.w),
                           pk2(bh.x, bh.y), pk2(bh.z, bh.w) };
            float av[8] = { al.x, al.y, al.z, al.w, ah.x, ah.y, ah.z, ah.w };
            #pragma unroll
            for (int i = 0; i < 8; i++) {
                ull ad = pk2(av[i], av[i]);
                #pragma unroll
                for (int jn = 0; jn < 4; jn++) fm2(acc[i][jn], ad, bb2[jn]);
            }
        }

        if (more) {
            int nbuf = buf ^ 1;
            As[nbuf][kcA * 4 + 0][mA] = na0.x;  As[nbuf][kcA * 4 + 1][mA] = na0.y;
            As[nbuf][kcA * 4 + 2][mA] = na0.z;  As[nbuf][kcA * 4 + 3][mA] = na0.w;
            As[nbuf][kcA * 4 + 0][mA + 64] = na1.x;  As[nbuf][kcA * 4 + 1][mA + 64] = na1.y;
            As[nbuf][kcA * 4 + 2][mA + 64] = na1.z;  As[nbuf][kcA * 4 + 3][mA + 64] = na1.w;
            *(float4*)&Bs[nbuf][kbB][ncB * 4]     = nb0v;
            *(float4*)&Bs[nbuf][kbB + 8][ncB * 4] = nb1v;
            __syncthreads();
        }
    }

    int mBase = by * TBM + ty * 8;
    int nIn   = nb0 + tx * 8;
    int nOut  = bx * TBN + tx * 8;
    float4 bvl = *(const float4*)(bias + nIn);
    float4 bvh = *(const float4*)(bias + nIn + 4);
    #pragma unroll
    for (int i = 0; i < 8; i++) {
        float2 p0 = up2(acc[i][0]), p1 = up2(acc[i][1]);
        float2 p2 = up2(acc[i][2]), p3 = up2(acc[i][3]);
        float4 c0 = make_float4(p0.x + bvl.x, p0.y + bvl.y, p1.x + bvl.z, p1.y + bvl.w);
        float4 c1 = make_float4(p2.x + bvh.x, p2.y + bvh.y, p3.x + bvh.z, p3.y + bvh.w);
        float* cp = C + (size_t)(mBase + i) * NC + nOut;
        *(float4*)cp = c0;
        *(float4*)(cp + 4) = c1;
    }
}

// ---------------- recurrence: R7/R12 structure (measured best) --------------
__device__ __forceinline__ void mbar_wait_tx(uint32_t mbar, uint32_t parity) {
    uint32_t done;
    asm volatile("{\n\t.reg .pred p;\n\t"
                 "mbarrier.try_wait.parity.acquire.cta.shared::cta.b64 p, [%1], %2;\n\t"
                 "selp.b32 %0, 1, 0, p;\n\t}"
                 : "=r"(done) : "r"(mbar), "r"(parity) : "memory");
    if (!done) {
        asm volatile("{\n\t.reg .pred P1;\n\t"
                     "WL_%=:\n\t"
                     "mbarrier.try_wait.parity.acquire.cta.shared::cta.b64 P1, [%0], %1, 0x989680;\n\t"
                     "@P1 bra.uni WD_%=;\n\t"
                     "bra.uni WL_%=;\n\t"
                     "WD_%=:\n\t}"
                     :: "r"(mbar), "r"(parity) : "memory");
    }
}

__global__ void __launch_bounds__(512, 1) __cluster_dims__(8, 1, 1)
rnn_scan(const float* __restrict__ Wh_f, const float* __restrict__ Wh_b) {
    __shared__ __align__(16) float hbuf[2048];   // [buf2][kq8][b2][64] = 8KB
    __shared__ __align__(16) float part[1024];   // [kq*2+b][64]
    __shared__ __align__(16) float stage[256];   // [par2][b2][64] = 2x512B
    __shared__ __align__(8)  ull  mb[2];

    int tid  = threadIdx.x;
    int bid  = blockIdx.x;
    int rank = bid & 7;
    int cid  = bid >> 3;
    int dir  = cid >> 3;
    int b0   = (cid & 7) * 2;
    int jbase = rank * 64;
    const float* __restrict__ Wh = dir ? Wh_b : Wh_f;

    int j  = tid & 63;
    int kq = tid >> 6;          // warp-pair-uniform
    int kb = kq * 64;
    int jg = jbase + j;

    ull w[32];
    #pragma unroll
    for (int c = 0; c < 32; c++)
        w[c] = pk2(__ldg(&Wh[(size_t)(kb + 2*c) * H_ + jg]),
                   __ldg(&Wh[(size_t)(kb + 2*c + 1) * H_ + jg]));

    for (int i = tid; i < 2048; i += 512) hbuf[i] = 0.f;

    uint32_t hb_s = (uint32_t)__cvta_generic_to_shared(hbuf);
    uint32_t st_s = (uint32_t)__cvta_generic_to_shared(stage);
    uint32_t mb_s = (uint32_t)__cvta_generic_to_shared(mb);

    if (tid == 0) {
        asm volatile("mbarrier.init.shared.b64 [%0], 1;" :: "r"(mb_s)     : "memory");
        asm volatile("mbarrier.init.shared.b64 [%0], 1;" :: "r"(mb_s + 8) : "memory");
        asm volatile("mbarrier.arrive.expect_tx.shared.b64 _, [%0], %1;"
                     :: "r"(mb_s + 8), "r"(4096u) : "memory");
        asm volatile("mbarrier.arrive.expect_tx.shared.b64 _, [%0], %1;"
                     :: "r"(mb_s), "r"(4096u) : "memory");
    }
    __syncthreads();
    asm volatile("barrier.cluster.arrive.aligned;" ::: "memory");
    asm volatile("barrier.cluster.wait.aligned;"   ::: "memory");

    uint32_t pbme;
    {
        int tgt = tid & 7;
        asm("mapa.shared::cluster.u32 %0, %1, %2;" : "=r"(pbme) : "r"(hb_s), "r"(tgt));
    }
    uint32_t dmb = mb_s - hb_s;

    int rj = tid & 63, rb = (tid >> 6) & 1;
    const float* prer = &g_pre[(size_t)(b0 + rb) * L_ * 1024 + dir * 512 + jbase + rj];
    float*       hsr  = &g_hs [(size_t)(b0 + rb) * L_ * 1024 + dir * 512 + jbase + rj];
    int t0 = dir ? (L_ - 1) : 0;
    float pv = (tid < 128) ? __ldg(prer + (size_t)t0 * 1024) : 0.f;

    for (int s = 0; s < L_; s++) {
        int t = dir ? (L_ - 1 - s) : s;

        if (s) {
            uint32_t par = (s & 1) ? ((s >> 1) & 1) : (((s >> 1) + 1) & 1);
            mbar_wait_tx(mb_s + 8 * (s & 1), par);
            if (tid == 0 && s + 2 < L_)
                asm volatile("mbarrier.arrive.expect_tx.shared.b64 _, [%0], %1;"
                             :: "r"(mb_s + 8 * (s & 1)), "r"(4096u) : "memory");
        }

        float nv = 0.f;
        if (tid < 128 && s + 1 < L_) {
            int tn = dir ? (L_ - 2 - s) : (s + 1);
            nv = __ldg(prer + (size_t)tn * 1024);
        }

        const float* hp = hbuf + (s & 1) * 1024 + kq * 128;
        ull a0 = 0ull, a1 = 0ull, a2 = 0ull, a3 = 0ull;
        #pragma unroll
        for (int c = 0; c < 16; c++) {
            ulonglong2 h0 = *(const ulonglong2*)(hp + 4 * c);
            ulonglong2 h1 = *(const ulonglong2*)(hp + 64 + 4 * c);
            fm2(a0, w[2*c],     h0.x);
            fm2(a1, w[2*c + 1], h0.y);
            fm2(a2, w[2*c],     h1.x);
            fm2(a3, w[2*c + 1], h1.y);
        }
        float2 u0 = up2(a0), u1 = up2(a1), u2 = up2(a2), u3 = up2(a3);
        part[(kq * 2 + 0) * 64 + j] = (u0.x + u0.y) + (u1.x + u1.y);
        part[(kq * 2 + 1) * 64 + j] = (u2.x + u2.y) + (u3.x + u3.y);
        __syncthreads();

        if (tid < 128) {
            float sum = pv;
            #pragma unroll
            for (int q = 0; q < 8; q++) sum += part[(q * 2 + rb) * 64 + rj];
            float hn = ftanh(sum);
            stage[((s + 1) & 1) * 128 + rb * 64 + rj] = hn;
            hsr[(size_t)t * 1024] = hn;

            if (s + 1 < L_) {
                asm volatile("bar.sync 1, 128;" ::: "memory");
                if (tid < 8) {
                    asm volatile("fence.proxy.async.shared::cta;" ::: "memory");
                    uint32_t nxt = (uint32_t)((s + 1) & 1);
                    uint32_t src = st_s + nxt * 512;
                    uint32_t dst = pbme + nxt * 4096 + (uint32_t)rank * 512;
                    uint32_t bar = pbme + dmb + 8 * nxt;
                    asm volatile(
                        "cp.async.bulk.shared::cluster.shared::cta.mbarrier::complete_tx::bytes "
                        "[%0], [%1], %2, [%3];"
                        :: "r"(dst), "r"(src), "r"(512u), "r"(bar) : "memory");
                }
            }
        }
        pv = nv;
    }
    asm volatile("barrier.cluster.arrive.aligned;" ::: "memory");
    asm volatile("barrier.cluster.wait.aligned;"   ::: "memory");
}

// ---------------- host ------------------------------------------------------
extern "C" void kernel_launch(void* const* d_in, const int* in_sizes, int n_in,
                              void* d_out, int out_size) {
    const float* x    = (const float*)d_in[0];
    // d_in[1] = c (unused by reference)
    const float* Wx_f = (const float*)d_in[2];
    const float* Wh_f = (const float*)d_in[3];
    const float* b_f  = (const float*)d_in[4];
    const float* Wo_f = (const float*)d_in[5];
    const float* bo_f = (const float*)d_in[6];
    const float* Wx_b = (const float*)d_in[7];
    const float* Wh_b = (const float*)d_in[8];
    const float* b_b  = (const float*)d_in[9];
    const float* Wo_b = (const float*)d_in[10];
    const float* bo_b = (const float*)d_in[11];
    const float* Wd   = (const float*)d_in[12];
    const float* bd   = (const float*)d_in[13];
    float* out = (float*)d_out;

    void *p_pre, *p_hs, *p_wc, *p_b2;
    cudaGetSymbolAddress(&p_pre, g_pre);
    cudaGetSymbolAddress(&p_hs,  g_hs);
    cudaGetSymbolAddress(&p_wc,  g_wcomb);
    cudaGetSymbolAddress(&p_b2,  g_bias2);

    // side stream + events (host objects only; created once, reused)
    static cudaStream_t s1 = nullptr;
    static cudaEvent_t evFork = nullptr, evJoin = nullptr;
    if (!s1) {
        cudaStreamCreateWithFlags(&s1, cudaStreamNonBlocking);
        cudaEventCreateWithFlags(&evFork, cudaEventDisableTiming);
        cudaEventCreateWithFlags(&evJoin, cudaEventDisableTiming);
    }

    // pre = x @ [Wx_f|Wx_b] + [b_f|b_b]
    {
        dim3 g(8, (B_ * L_) / TBM);
        sgemm_pre<<<g, 256>>>(x, Wx_f, Wx_b, b_f, b_b, (float*)p_pre);
    }

    // fork side chain onto s1 (independent of pre/scan; runs on spare SMs)
    cudaEventRecord(evFork, 0);
    cudaStreamWaitEvent(s1, evFork, 0);

    // side chain (s1): Wcomb + bias2 — overlapped with the scan
    {
        dim3 g(512 / TBN, 512 / TBM);
        sgemm<<<g, 256, 0, s1>>>(Wo_f, Wd, nullptr, (float*)p_wc, 512, 512, 512);
        sgemm<<<g, 256, 0, s1>>>(Wo_b, Wd + 512 * 512, nullptr,
                                 (float*)p_wc + 512 * 512, 512, 512, 512);
    }
    bias2_kernel<<<1, 512, 0, s1>>>(Wd, bd, bo_f, bo_b);

    // bidirectional scan
    {
        cudaLaunchConfig_t cfg = {};
        cfg.gridDim = dim3(128, 1, 1);
        cfg.blockDim = dim3(512, 1, 1);
        cfg.dynamicSmemBytes = 0;
        cfg.stream = 0;
        cudaLaunchAttribute at[1];
        at[0].id = cudaLaunchAttributeClusterDimension;
        at[0].val.clusterDim.x = 8; at[0].val.clusterDim.y = 1; at[0].val.clusterDim.z = 1;
        cfg.attrs = at;
        cfg.numAttrs = 1;
        cudaLaunchKernelEx(&cfg, rnn_scan, Wh_f, Wh_b);
    }

    // join side chain before the final GEMM
    cudaEventRecord(evJoin, s1);
    cudaStreamWaitEvent(0, evJoin, 0);

    // out = hs @ Wcomb + bias2
    {
        dim3 g(512 / TBN, (B_ * L_) / TBM);
        sgemm<<<g, 256>>>((const float*)p_hs, (const float*)p_wc,
                          (const float*)p_b2, out, B_ * L_, 512, 1024);
    }
}